// round 14
// baseline (speedup 1.0000x reference)
#include <cuda_runtime.h>

// Direction table: E = 2,000,000 edges; float4 for 16B-aligned gathers.
// 2.1M * 16B = 33.6 MB static __device__ array; fully L2-resident (126 MB L2).
#define MAX_E 2100000

static __device__ float4 g_dir[MAX_E];
static __device__ int    g_idx_is64;

// ---------------------------------------------------------------------------
// Cache-policy load/store helpers
// ---------------------------------------------------------------------------
__device__ __forceinline__ unsigned long long evict_last_policy()
{
    unsigned long long pol;
    asm volatile("createpolicy.fractional.L2::evict_last.b64 %0, 1.0;" : "=l"(pol));
    return pol;
}

__device__ __forceinline__ float4 ldg_table(const float4* p, unsigned long long pol)
{
    float4 v;
    asm volatile("ld.global.nc.L2::cache_hint.v4.f32 {%0,%1,%2,%3}, [%4], %5;"
                 : "=f"(v.x), "=f"(v.y), "=f"(v.z), "=f"(v.w)
                 : "l"(p), "l"(pol));
    return v;
}

__device__ __forceinline__ longlong2 ldcs_ll2(const longlong2* p)
{
    longlong2 v;
    asm volatile("ld.global.cs.v2.s64 {%0,%1}, [%2];"
                 : "=l"(v.x), "=l"(v.y) : "l"(p));
    return v;
}

__device__ __forceinline__ int4 ldcs_i4(const int4* p)
{
    int4 v;
    asm volatile("ld.global.cs.v4.s32 {%0,%1,%2,%3}, [%4];"
                 : "=r"(v.x), "=r"(v.y), "=r"(v.z), "=r"(v.w) : "l"(p));
    return v;
}

__device__ __forceinline__ void stcs_f4(float4* p, float4 v)
{
    asm volatile("st.global.cs.v4.f32 [%0], {%1,%2,%3,%4};"
                 :: "l"(p), "f"(v.x), "f"(v.y), "f"(v.z), "f"(v.w) : "memory");
}

__device__ __forceinline__ void pdl_launch_dependents()
{
    asm volatile("griddepcontrol.launch_dependents;");
}

__device__ __forceinline__ void pdl_wait()
{
    asm volatile("griddepcontrol.wait;");
}

// ---------------------------------------------------------------------------
// Pass 1: dir[i] = vec[i] / max(dist[i], 1e-5).
// 1024 edges per 256-thread block. vec is staged through SMEM with coalesced
// float4 loads (4x fewer global load instructions, coalescing preserved);
// dist loaded as one float4 per thread (aligned with its 4 edges).
// Block 0 / warp 0 detects int64-vs-int32 indices; all blocks then trigger
// PDL so the angle kernel overlaps its launch + index prologue.
// ---------------------------------------------------------------------------
__global__ void __launch_bounds__(256) dir_kernel(
        const float* __restrict__ dist,
        const float* __restrict__ vec,
        const unsigned int* __restrict__ idx_words,
        int n_pairs,
        int E)
{
    __shared__ float svec[3072];   // 1024 edges * 3 comps = 12 KB

    if (blockIdx.x == 0 && threadIdx.x < 32) {
        int n = n_pairs < 256 ? n_pairs : 256;
        int lane = threadIdx.x;
        int zeros = 0;
        for (int j = lane; j < n; j += 32)
            zeros += (idx_words[2 * j + 1] == 0u) ? 1 : 0;
        #pragma unroll
        for (int off = 16; off > 0; off >>= 1)
            zeros += __shfl_down_sync(0xFFFFFFFFu, zeros, off);
        if (lane == 0) {
            g_idx_is64 = (zeros >= (n * 3) / 4) ? 1 : 0;
            __threadfence();
        }
    }
    __syncthreads();          // flag write ordered before trigger
    pdl_launch_dependents();

    int base = blockIdx.x * 1024;
    int t = threadIdx.x;

    if (base + 1024 <= E) {
        // Coalesced staging of this block's vec range [3*base, 3*base+3072).
        const float4* vp = (const float4*)(vec + 3 * base);
        #pragma unroll
        for (int j = 0; j < 3; ++j)
            ((float4*)svec)[t + j * 256] = vp[t + j * 256];

        float4 d4 = ((const float4*)(dist + base))[t];
        __syncthreads();

        int e0 = base + 4 * t;
        const float* sv = &svec[12 * t];
        float i0 = 1.0f / fmaxf(d4.x, 1e-5f);
        float i1 = 1.0f / fmaxf(d4.y, 1e-5f);
        float i2 = 1.0f / fmaxf(d4.z, 1e-5f);
        float i3 = 1.0f / fmaxf(d4.w, 1e-5f);
        g_dir[e0 + 0] = make_float4(sv[0] * i0, sv[1]  * i0, sv[2]  * i0, 0.0f);
        g_dir[e0 + 1] = make_float4(sv[3] * i1, sv[4]  * i1, sv[5]  * i1, 0.0f);
        g_dir[e0 + 2] = make_float4(sv[6] * i2, sv[7]  * i2, sv[8]  * i2, 0.0f);
        g_dir[e0 + 3] = make_float4(sv[9] * i3, sv[10] * i3, sv[11] * i3, 0.0f);
    } else {
        // Partial last block: scalar, coalesced per-float loads.
        for (int i = base + t; i < E; i += 256) {
            float inv = 1.0f / fmaxf(dist[i], 1e-5f);
            g_dir[i] = make_float4(vec[3 * i] * inv, vec[3 * i + 1] * inv,
                                   vec[3 * i + 2] * inv, 0.0f);
        }
    }
}

// ---------------------------------------------------------------------------
// Pass 2: 4 angle pairs per thread, 128-thread blocks (finer retire
// granularity halves the end-of-kernel drain bubble), gathers in two
// batches of 4 to keep live registers <= 32 (16 blocks/SM). Streamed index
// loads (evict-first), evict-last table gathers, streamed vector stores.
// PDL: index loads overlap dir_kernel; gathers gated by griddepcontrol.wait.
// ---------------------------------------------------------------------------
__global__ void __launch_bounds__(128, 16) angle_kernel(
        const void* __restrict__ src_v,
        const void* __restrict__ dst_v,
        float* __restrict__ out,
        int A)
{
    int t  = blockIdx.x * blockDim.x + threadIdx.x;
    int i0 = t * 4;
    if (i0 >= A) { pdl_wait(); return; }

    unsigned long long pol = evict_last_policy();
    const int is64 = g_idx_is64;   // written before dir_kernel's PDL trigger

    if (i0 + 3 < A) {
        int s[4], d[4];
        if (is64) {
            const long long* sp = (const long long*)src_v + i0;
            const long long* dp = (const long long*)dst_v + i0;
            longlong2 sa = ldcs_ll2((const longlong2*)sp);
            longlong2 sb = ldcs_ll2((const longlong2*)(sp + 2));
            longlong2 da = ldcs_ll2((const longlong2*)dp);
            longlong2 db = ldcs_ll2((const longlong2*)(dp + 2));
            s[0] = (int)sa.x; s[1] = (int)sa.y; s[2] = (int)sb.x; s[3] = (int)sb.y;
            d[0] = (int)da.x; d[1] = (int)da.y; d[2] = (int)db.x; d[3] = (int)db.y;
        } else {
            int4 sa = ldcs_i4((const int4*)((const int*)src_v + i0));
            int4 da = ldcs_i4((const int4*)((const int*)dst_v + i0));
            s[0] = sa.x; s[1] = sa.y; s[2] = sa.z; s[3] = sa.w;
            d[0] = da.x; d[1] = da.y; d[2] = da.z; d[3] = da.w;
        }

        // Gate the table gathers on dir_kernel completion.
        pdl_wait();

        // Batch 1: 4 gathers in flight, consume, release registers.
        float4 a0 = ldg_table(&g_dir[s[0]], pol);
        float4 b0 = ldg_table(&g_dir[d[0]], pol);
        float4 a1 = ldg_table(&g_dir[s[1]], pol);
        float4 b1 = ldg_table(&g_dir[d[1]], pol);
        float c0 = a0.x * b0.x + a0.y * b0.y + a0.z * b0.z;
        float c1 = a1.x * b1.x + a1.y * b1.y + a1.z * b1.z;
        float r0 = acosf(0.95f * c0);
        float r1 = acosf(0.95f * c1);

        // Batch 2.
        float4 a2 = ldg_table(&g_dir[s[2]], pol);
        float4 b2 = ldg_table(&g_dir[d[2]], pol);
        float4 a3 = ldg_table(&g_dir[s[3]], pol);
        float4 b3 = ldg_table(&g_dir[d[3]], pol);
        float c2 = a2.x * b2.x + a2.y * b2.y + a2.z * b2.z;
        float c3 = a3.x * b3.x + a3.y * b3.y + a3.z * b3.z;

        float4 r = make_float4(r0, r1, acosf(0.95f * c2), acosf(0.95f * c3));
        stcs_f4((float4*)(out + i0), r);
    } else {
        pdl_wait();
        for (int i = i0; i < A; ++i) {
            int si, di;
            if (is64) {
                si = (int)((const long long*)src_v)[i];
                di = (int)((const long long*)dst_v)[i];
            } else {
                si = ((const int*)src_v)[i];
                di = ((const int*)dst_v)[i];
            }
            float4 a = ldg_table(&g_dir[si], pol);
            float4 b = ldg_table(&g_dir[di], pol);
            float c = a.x * b.x + a.y * b.y + a.z * b.z;
            out[i] = acosf(0.95f * c);
        }
    }
}

// ---------------------------------------------------------------------------
// Launch
// inputs (metadata order): distances [E] f32, vec [E,3] f32,
//                          angle_src [A] i64/i32, angle_dst [A] i64/i32
// output: angles [A] f32
// ---------------------------------------------------------------------------
extern "C" void kernel_launch(void* const* d_in, const int* in_sizes, int n_in,
                              void* d_out, int out_size)
{
    const float* dist = (const float*)d_in[0];
    const float* vec  = (const float*)d_in[1];
    const void*  src  = d_in[2];
    const void*  dst  = d_in[3];
    float*       out  = (float*)d_out;

    int E = in_sizes[0];
    int A = in_sizes[2];
    if (E > MAX_E) E = MAX_E;

    int dir_blocks = (E + 1023) / 1024;
    dir_kernel<<<dir_blocks, 256>>>(dist, vec, (const unsigned int*)src, A, E);

    // Angle kernel with programmatic dependent launch.
    const int T = 128;
    int threads_needed = (A + 3) / 4;
    int blocks = (threads_needed + T - 1) / T;

    cudaLaunchConfig_t cfg = {};
    cfg.gridDim  = dim3((unsigned)blocks, 1, 1);
    cfg.blockDim = dim3((unsigned)T, 1, 1);
    cfg.dynamicSmemBytes = 0;
    cfg.stream = 0;

    cudaLaunchAttribute attrs[1];
    attrs[0].id = cudaLaunchAttributeProgrammaticStreamSerialization;
    attrs[0].val.programmaticStreamSerializationAllowed = 1;
    cfg.attrs = attrs;
    cfg.numAttrs = 1;

    cudaLaunchKernelEx(&cfg, angle_kernel, (const void*)src, (const void*)dst, out, A);
}

// round 15
// speedup vs baseline: 1.0410x; 1.0410x over previous
#include <cuda_runtime.h>

// Direction table: E = 2,000,000 edges; float4 for 16B-aligned gathers.
// 2.1M * 16B = 33.6 MB static __device__ array; fully L2-resident (126 MB L2).
#define MAX_E 2100000

static __device__ float4 g_dir[MAX_E];
static __device__ int    g_idx_is64;

// ---------------------------------------------------------------------------
// Cache-policy load/store helpers
// ---------------------------------------------------------------------------
__device__ __forceinline__ unsigned long long evict_last_policy()
{
    unsigned long long pol;
    asm volatile("createpolicy.fractional.L2::evict_last.b64 %0, 1.0;" : "=l"(pol));
    return pol;
}

__device__ __forceinline__ float4 ldg_table(const float4* p, unsigned long long pol)
{
    float4 v;
    asm volatile("ld.global.nc.L2::cache_hint.v4.f32 {%0,%1,%2,%3}, [%4], %5;"
                 : "=f"(v.x), "=f"(v.y), "=f"(v.z), "=f"(v.w)
                 : "l"(p), "l"(pol));
    return v;
}

__device__ __forceinline__ longlong2 ldcs_ll2(const longlong2* p)
{
    longlong2 v;
    asm volatile("ld.global.cs.v2.s64 {%0,%1}, [%2];"
                 : "=l"(v.x), "=l"(v.y) : "l"(p));
    return v;
}

__device__ __forceinline__ int4 ldcs_i4(const int4* p)
{
    int4 v;
    asm volatile("ld.global.cs.v4.s32 {%0,%1,%2,%3}, [%4];"
                 : "=r"(v.x), "=r"(v.y), "=r"(v.z), "=r"(v.w) : "l"(p));
    return v;
}

__device__ __forceinline__ void stcs_f4(float4* p, float4 v)
{
    asm volatile("st.global.cs.v4.f32 [%0], {%1,%2,%3,%4};"
                 :: "l"(p), "f"(v.x), "f"(v.y), "f"(v.z), "f"(v.w) : "memory");
}

__device__ __forceinline__ void pdl_launch_dependents()
{
    asm volatile("griddepcontrol.launch_dependents;");
}

__device__ __forceinline__ void pdl_wait()
{
    asm volatile("griddepcontrol.wait;");
}

// ---------------------------------------------------------------------------
// Pass 1: dir[i] = vec[i] / max(dist[i], 1e-5).
// Scalar 1-edge/thread (fastest variant measured: consecutive threads read
// consecutive floats -> fully coalesced; SMEM/float4 variants regressed).
// dist/vec reads use .cs (evict-first) so this 32 MB single-use stream does
// not displace the dir table from L2 right before the gather phase.
// Block 0 / warp 0 detects int64-vs-int32 indices; all blocks then trigger
// PDL so the angle kernel overlaps its launch + index prologue.
// ---------------------------------------------------------------------------
__global__ void dir_kernel(const float* __restrict__ dist,
                           const float* __restrict__ vec,
                           const unsigned int* __restrict__ idx_words,
                           int n_pairs,
                           int E)
{
    if (blockIdx.x == 0 && threadIdx.x < 32) {
        int n = n_pairs < 256 ? n_pairs : 256;
        int lane = threadIdx.x;
        int zeros = 0;
        for (int j = lane; j < n; j += 32)
            zeros += (idx_words[2 * j + 1] == 0u) ? 1 : 0;
        #pragma unroll
        for (int off = 16; off > 0; off >>= 1)
            zeros += __shfl_down_sync(0xFFFFFFFFu, zeros, off);
        if (lane == 0) {
            g_idx_is64 = (zeros >= (n * 3) / 4) ? 1 : 0;
            __threadfence();
        }
    }
    __syncthreads();          // flag write ordered before trigger
    pdl_launch_dependents();

    int i = blockIdx.x * blockDim.x + threadIdx.x;
    if (i >= E) return;
    float inv = 1.0f / fmaxf(__ldcs(dist + i), 1e-5f);
    float x = __ldcs(vec + 3 * i + 0) * inv;
    float y = __ldcs(vec + 3 * i + 1) * inv;
    float z = __ldcs(vec + 3 * i + 2) * inv;
    g_dir[i] = make_float4(x, y, z, 0.0f);
}

// ---------------------------------------------------------------------------
// Pass 2: 4 angle pairs per thread, gathers in two batches of 4 to keep the
// live register set <= 32 regs (launch_bounds(256,8) -> high occupancy).
// Streamed index loads (evict-first), evict-last table gathers, streamed
// vector output stores. PDL: index loads overlap dir_kernel's tail;
// griddepcontrol.wait gates the table gathers on dir_kernel completion.
// ---------------------------------------------------------------------------
__global__ void __launch_bounds__(256, 8) angle_kernel(
        const void* __restrict__ src_v,
        const void* __restrict__ dst_v,
        float* __restrict__ out,
        int A)
{
    int t  = blockIdx.x * blockDim.x + threadIdx.x;
    int i0 = t * 4;
    if (i0 >= A) { pdl_wait(); return; }

    unsigned long long pol = evict_last_policy();
    const int is64 = g_idx_is64;   // written before dir_kernel's PDL trigger

    if (i0 + 3 < A) {
        int s[4], d[4];
        if (is64) {
            const long long* sp = (const long long*)src_v + i0;
            const long long* dp = (const long long*)dst_v + i0;
            longlong2 sa = ldcs_ll2((const longlong2*)sp);
            longlong2 sb = ldcs_ll2((const longlong2*)(sp + 2));
            longlong2 da = ldcs_ll2((const longlong2*)dp);
            longlong2 db = ldcs_ll2((const longlong2*)(dp + 2));
            s[0] = (int)sa.x; s[1] = (int)sa.y; s[2] = (int)sb.x; s[3] = (int)sb.y;
            d[0] = (int)da.x; d[1] = (int)da.y; d[2] = (int)db.x; d[3] = (int)db.y;
        } else {
            int4 sa = ldcs_i4((const int4*)((const int*)src_v + i0));
            int4 da = ldcs_i4((const int4*)((const int*)dst_v + i0));
            s[0] = sa.x; s[1] = sa.y; s[2] = sa.z; s[3] = sa.w;
            d[0] = da.x; d[1] = da.y; d[2] = da.z; d[3] = da.w;
        }

        // Gate the table gathers on dir_kernel completion.
        pdl_wait();

        // Batch 1: 4 gathers in flight, consume, release registers.
        float4 a0 = ldg_table(&g_dir[s[0]], pol);
        float4 b0 = ldg_table(&g_dir[d[0]], pol);
        float4 a1 = ldg_table(&g_dir[s[1]], pol);
        float4 b1 = ldg_table(&g_dir[d[1]], pol);
        float c0 = a0.x * b0.x + a0.y * b0.y + a0.z * b0.z;
        float c1 = a1.x * b1.x + a1.y * b1.y + a1.z * b1.z;
        float r0 = acosf(0.95f * c0);
        float r1 = acosf(0.95f * c1);

        // Batch 2.
        float4 a2 = ldg_table(&g_dir[s[2]], pol);
        float4 b2 = ldg_table(&g_dir[d[2]], pol);
        float4 a3 = ldg_table(&g_dir[s[3]], pol);
        float4 b3 = ldg_table(&g_dir[d[3]], pol);
        float c2 = a2.x * b2.x + a2.y * b2.y + a2.z * b2.z;
        float c3 = a3.x * b3.x + a3.y * b3.y + a3.z * b3.z;

        float4 r = make_float4(r0, r1, acosf(0.95f * c2), acosf(0.95f * c3));
        stcs_f4((float4*)(out + i0), r);
    } else {
        pdl_wait();
        for (int i = i0; i < A; ++i) {
            int si, di;
            if (is64) {
                si = (int)((const long long*)src_v)[i];
                di = (int)((const long long*)dst_v)[i];
            } else {
                si = ((const int*)src_v)[i];
                di = ((const int*)dst_v)[i];
            }
            float4 a = ldg_table(&g_dir[si], pol);
            float4 b = ldg_table(&g_dir[di], pol);
            float c = a.x * b.x + a.y * b.y + a.z * b.z;
            out[i] = acosf(0.95f * c);
        }
    }
}

// ---------------------------------------------------------------------------
// Launch
// inputs (metadata order): distances [E] f32, vec [E,3] f32,
//                          angle_src [A] i64/i32, angle_dst [A] i64/i32
// output: angles [A] f32
// ---------------------------------------------------------------------------
extern "C" void kernel_launch(void* const* d_in, const int* in_sizes, int n_in,
                              void* d_out, int out_size)
{
    const float* dist = (const float*)d_in[0];
    const float* vec  = (const float*)d_in[1];
    const void*  src  = d_in[2];
    const void*  dst  = d_in[3];
    float*       out  = (float*)d_out;

    int E = in_sizes[0];
    int A = in_sizes[2];
    if (E > MAX_E) E = MAX_E;

    const int T = 256;
    dir_kernel<<<(E + T - 1) / T, T>>>(dist, vec, (const unsigned int*)src, A, E);

    // Angle kernel with programmatic dependent launch: overlaps its index
    // prologue with dir_kernel's tail.
    int threads_needed = (A + 3) / 4;
    int blocks = (threads_needed + T - 1) / T;

    cudaLaunchConfig_t cfg = {};
    cfg.gridDim  = dim3((unsigned)blocks, 1, 1);
    cfg.blockDim = dim3((unsigned)T, 1, 1);
    cfg.dynamicSmemBytes = 0;
    cfg.stream = 0;

    cudaLaunchAttribute attrs[1];
    attrs[0].id = cudaLaunchAttributeProgrammaticStreamSerialization;
    attrs[0].val.programmaticStreamSerializationAllowed = 1;
    cfg.attrs = attrs;
    cfg.numAttrs = 1;

    cudaLaunchKernelEx(&cfg, angle_kernel, (const void*)src, (const void*)dst, out, A);
}